// round 14
// baseline (speedup 1.0000x reference)
#include <cuda_runtime.h>

#define W_      10
#define NSTATE  4096
#define BATCH   512
#define NIN     6
#define STAGES  2

typedef unsigned long long u64;

#define NEGB   0x8000000080000000ULL
#define MASKP  0x0000000080000000ULL
#define MASKM  0x8000000000000000ULL

// Per-sweep, thread-major coefficient table:
// sw_tab[((s*5+sw)*256 + t)*8 + j] = (cos(phi/2), sin(phi/2)) for the j-th
// coefficient consumed by thread t in neuron sweep sw of stage s.
// j<4: neuron A=2sw at group jj=j; j>=4: neuron B=2sw+1 at group jj=j-4.
__device__ float2 sw_tab[STAGES * 5 * 256 * 8];
__device__ float2 u_tab[STAGES * W_];

__global__ void precompute_kernel(const float* __restrict__ unitary_theta,
                                  const float* __restrict__ neuron_theta) {
    int idx = blockIdx.x * blockDim.x + threadIdx.x;
    if (idx < STAGES * 5 * 256 * 8) {
        int j   = idx & 7;
        int t   = (idx >> 3) & 255;
        int sw  = (idx >> 11) % 5;
        int s   = idx >> 11  / 1 >= 0 ? (idx >> 11) / 5 : 0;   // stage
        int n   = 2 * sw + (j >> 2);          // neuron index
        int jj  = j & 3;                       // group selector
        int g;
        if (sw < 4) {
            int PA = 11 - 2 * sw;
            int LB = PA - 3;
            int low  = t & ((1 << LB) - 1);
            int high = t >> LB;
            int gb   = low | (high << (PA - 1));
            g = gb + ((jj & 1) << (PA - 3)) + ((jj >> 1) << (PA - 2));
        } else {
            g = (t << 2) + jj;
        }
        const float* th = neuron_theta + (s * W_ + n) * (W_ + 1);
        float phi = th[W_];
        #pragma unroll
        for (int i = 0; i < W_; i++)
            if ((g >> (9 - i)) & 1) phi += th[i];
        float sv, cv;
        sincosf(phi * 0.5f, &sv, &cv);
        sw_tab[idx] = make_float2(cv, sv);
    }
    if (idx < STAGES * W_) {
        float sv, cv;
        sincosf(unitary_theta[idx] * 0.5f, &sv, &cv);
        u_tab[idx] = make_float2(cv, sv);
    }
}

// ---- f32x2 primitives ----
__device__ __forceinline__ u64 pk2(float lo, float hi) {
    u64 r; asm("mov.b64 %0, {%1,%2};" : "=l"(r) : "f"(lo), "f"(hi)); return r;
}
__device__ __forceinline__ u64 bcast(float v) { return pk2(v, v); }
__device__ __forceinline__ u64 f2mul(u64 a, u64 b) {
    u64 r; asm("mul.rn.f32x2 %0, %1, %2;" : "=l"(r) : "l"(a), "l"(b)); return r;
}
__device__ __forceinline__ u64 f2fma(u64 a, u64 b, u64 c) {
    u64 r; asm("fma.rn.f32x2 %0, %1, %2, %3;" : "=l"(r) : "l"(a), "l"(b), "l"(c)); return r;
}
__device__ __forceinline__ u64 lswap(u64 a) {
    u64 r; asm("{.reg .b32 x,y; mov.b64 {x,y}, %1; mov.b64 %0, {y,x};}" : "=l"(r) : "l"(a)); return r;
}
__device__ __forceinline__ void xswapneg(u64& a, u64& b) {
    asm("{\n\t.reg .b32 al,ah,bl,bh;\n\t"
        "mov.b64 {al,ah}, %0;\n\t"
        "mov.b64 {bl,bh}, %1;\n\t"
        "neg.f32 bh, bh;\n\t"
        "mov.b64 %0, {al,bh};\n\t"
        "mov.b64 %1, {bl,ah};\n\t}"
        : "+l"(a), "+l"(b));
}

// ---- swizzle (proven conflict-free) ----
__device__ __forceinline__ int swG(int G) {
    return G ^ ( ((G >> 3) & 1)
               | (((G >> 4) & 1) << 1)
               | ((((G >> 5) ^ (G >> 4)) & 1) << 2) );
}
__device__ __forceinline__ int swE(int e) { return (swG(e >> 1) << 1) | (e & 1); }

__device__ __forceinline__ void ld2(const u64* sm, int g, u64& a, u64& b) {
    ulonglong2 v = *(const ulonglong2*)(sm + (swG(g) << 1)); a = v.x; b = v.y;
}
__device__ __forceinline__ void st2(u64* sm, int g, u64 a, u64 b) {
    *(ulonglong2*)(sm + (swG(g) << 1)) = make_ulonglong2(a, b);
}

// grp4p: RY(+phi) q10, CRY(sgn*pi) 10->11, RY(-phi) q10
__device__ __forceinline__ void grp4p(u64& qxy, u64& qzw,
                                      u64 cc, u64 ss, u64 nss, u64 umask) {
    u64 t01 = f2fma(cc, qxy, f2mul(nss, qzw));
    u64 t23 = f2fma(cc, qzw, f2mul(ss,  qxy));
    u64 u23 = lswap(t23) ^ umask;
    qxy = f2fma(cc, t01, f2mul(ss,  u23));
    qzw = f2fma(cc, u23, f2mul(nss, t01));
}
// full neuron on 8 amps (two packed groups)
__device__ __forceinline__ void neuron8p(u64& xy0, u64& zw0, u64& xy1, u64& zw1,
                                         float2 cs0, float2 cs1) {
    u64 cc0 = bcast(cs0.x), ss0 = bcast(cs0.y), nss0 = ss0 ^ NEGB;
    u64 cc1 = bcast(cs1.x), ss1 = bcast(cs1.y), nss1 = ss1 ^ NEGB;
    grp4p(xy0, zw0, cc0, ss0, nss0, MASKP);
    grp4p(xy1, zw1, cc1, ss1, nss1, MASKP);
    xswapneg(xy0, xy1);
    xswapneg(zw0, zw1);
    grp4p(xy0, zw0, cc0, ss0, nss0, MASKM);
    grp4p(xy1, zw1, cc1, ss1, nss1, MASKM);
}

// RY on bit `bit` of the 8-element u64 register index
__device__ __forceinline__ void ry8b(u64 R[8], int bit, float2 cs) {
    u64 cc = bcast(cs.x), ss = bcast(cs.y), nss = ss ^ NEGB;
    #pragma unroll
    for (int k = 0; k < 8; k++) {
        if (!((k >> bit) & 1)) {
            int k1 = k | (1 << bit);
            u64 a = R[k], b2 = R[k1];
            R[k]  = f2fma(cc, a, f2mul(nss, b2));
            R[k1] = f2fma(ss, a, f2mul(cc,  b2));
        }
    }
}

// Neuron pair with precoalesced coefficients T[0..7]:
// T[0..3] = neuron A at groups g00,g01,g10,g11; T[4..7] = neuron B same order.
template <int PA>
__device__ __forceinline__ void neuron_pairp(u64* sm, const float2* __restrict__ T,
                                             int t) {
    constexpr int PB = PA - 1;
    constexpr int LB = PB - 2;
    const int low  = t & ((1 << LB) - 1);
    const int high = t >> LB;
    const int gb   = low | (high << (PA - 1));

    const int g00 = gb;
    const int g01 = gb + (1 << (PB - 2));
    const int g10 = gb + (1 << (PA - 2));
    const int g11 = g10 + (1 << (PB - 2));

    // 4 coalesced 16B loads of 8 float2 coefficients
    float4 v0 = ((const float4*)T)[0];
    float4 v1 = ((const float4*)T)[1];
    float4 v2 = ((const float4*)T)[2];
    float4 v3 = ((const float4*)T)[3];

    u64 a0, b0, a1, b1, a2, b2, a3, b3;
    ld2(sm, g00, a0, b0); ld2(sm, g01, a1, b1);
    ld2(sm, g10, a2, b2); ld2(sm, g11, a3, b3);

    neuron8p(a0, b0, a2, b2, make_float2(v0.x, v0.y), make_float2(v1.x, v1.y)); // A: g00,g10
    neuron8p(a1, b1, a3, b3, make_float2(v0.z, v0.w), make_float2(v1.z, v1.w)); // A: g01,g11
    neuron8p(a0, b0, a1, b1, make_float2(v2.x, v2.y), make_float2(v2.z, v2.w)); // B: g00,g01
    neuron8p(a2, b2, a3, b3, make_float2(v3.x, v3.y), make_float2(v3.z, v3.w)); // B: g10,g11

    st2(sm, g00, a0, b0); st2(sm, g01, a1, b1);
    st2(sm, g10, a2, b2); st2(sm, g11, a3, b3);
}

__global__ void __launch_bounds__(256, 4) sim_kernel(
    const float* __restrict__ psi_in,
    const int*   __restrict__ inp,
    float*       __restrict__ probs_out,
    float*       __restrict__ psi_out)
{
    __shared__ __align__(16) u64 sm[NSTATE / 2];
    __shared__ float red[256];

    const int b = blockIdx.x;
    const int t = threadIdx.x;

    const int barP = 1 + ((t >> 5) & 1);   // ids 1,2 (parity groups, 128 thr)
    const int barQ = 3 + (t >> 6);         // ids 3..6 (2-warp groups, 64 thr)

    int mask = 0;
    #pragma unroll
    for (int l = 0; l < NIN; l++) mask |= (inp[l] & 1) << (11 - l);

    #pragma unroll
    for (int s = 0; s < STAGES; s++) {
        const float2* ut = &u_tab[s * W_];

        // ---- U-A: RY lanes 0,1,2 (e bits 10,9,8). e = t | (k<<8).
        {
            u64 R[8];
            if (s == 0) {
                const float* in = psi_in + (size_t)b * NSTATE;
                #pragma unroll
                for (int k = 0; k < 8; k++) {
                    int e = t | (k << 8);
                    R[k] = *(const u64*)(in + ((e << 1) ^ mask));
                }
            } else {
                #pragma unroll
                for (int k = 0; k < 8; k++) R[k] = sm[swE(t | (k << 8))];
            }
            ry8b(R, 2, ut[0]); ry8b(R, 1, ut[1]); ry8b(R, 0, ut[2]);
            #pragma unroll
            for (int k = 0; k < 8; k++) sm[swE(t | (k << 8))] = R[k];
        }
        __syncthreads();

        // ---- U-B: RY lanes 3,4,5 (e bits 7,6,5). Warp-local.
        {
            const int base = (t & 31) | ((t >> 5) << 8);
            u64 R[8];
            #pragma unroll
            for (int k = 0; k < 8; k++) R[k] = sm[swE(base | (k << 5))];
            ry8b(R, 2, ut[3]); ry8b(R, 1, ut[4]); ry8b(R, 0, ut[5]);
            #pragma unroll
            for (int k = 0; k < 8; k++) sm[swE(base | (k << 5))] = R[k];
        }
        __syncwarp();

        // ---- U-C: RY lanes 6,7,8 (e bits 4,3,2) + lane 9 (e bit 1) via shfl.
        {
            const int base = (t & 3) | ((t >> 2) << 5);
            u64 R[8];
            #pragma unroll
            for (int k = 0; k < 8; k++) R[k] = sm[swE(base | (k << 2))];
            ry8b(R, 2, ut[6]); ry8b(R, 1, ut[7]); ry8b(R, 0, ut[8]);
            {
                u64 cc = bcast(ut[9].x);
                u64 sp = bcast((t & 2) ? ut[9].y : -ut[9].y);
                #pragma unroll
                for (int k = 0; k < 8; k++) {
                    u64 o = __shfl_xor_sync(0xffffffffu, R[k], 2);
                    R[k] = f2fma(cc, R[k], f2mul(sp, o));
                }
            }
            #pragma unroll
            for (int k = 0; k < 8; k++) sm[swE(base | (k << 2))] = R[k];
        }
        __syncthreads();

        const float2* tbS = &sw_tab[(s * 5) * 256 * 8 + (t << 3)];

        // ---- neuron pairs (coefficients pre-coalesced per sweep)
        neuron_pairp<11>(sm, tbS + 0 * 2048, t);
        asm volatile("bar.sync %0, 128;" :: "r"(barP) : "memory");
        neuron_pairp<9 >(sm, tbS + 1 * 2048, t);
        asm volatile("bar.sync %0, 64;" :: "r"(barQ) : "memory");
        neuron_pairp<7 >(sm, tbS + 2 * 2048, t); __syncwarp();
        neuron_pairp<5 >(sm, tbS + 3 * 2048, t); __syncwarp();

        // ---- neurons 8,9 (group bits 1,0): 4 contiguous groups (warp-local reads).
        {
            const float2* T = tbS + 4 * 2048;
            float4 v0 = ((const float4*)T)[0];
            float4 v1 = ((const float4*)T)[1];
            float4 v2 = ((const float4*)T)[2];
            float4 v3 = ((const float4*)T)[3];
            const int G0 = t << 2;
            u64 a0, b0, a1, b1, a2, b2, a3, b3;
            ld2(sm, G0,     a0, b0); ld2(sm, G0 + 1, a1, b1);
            ld2(sm, G0 + 2, a2, b2); ld2(sm, G0 + 3, a3, b3);

            // A (neuron 8) at groups jj: T[0..3] = G0..G0+3 ; B (neuron 9) = T[4..7]
            neuron8p(a0, b0, a2, b2, make_float2(v0.x, v0.y), make_float2(v1.x, v1.y)); // A: G0,G0+2
            neuron8p(a1, b1, a3, b3, make_float2(v0.z, v0.w), make_float2(v1.z, v1.w)); // A: G0+1,G0+3
            neuron8p(a0, b0, a1, b1, make_float2(v2.x, v2.y), make_float2(v2.z, v2.w)); // B: G0,G0+1
            neuron8p(a2, b2, a3, b3, make_float2(v3.x, v3.y), make_float2(v3.z, v3.w)); // B: G0+2,G0+3

            if (s == STAGES - 1) {
                ulonglong2* out2 = (ulonglong2*)(psi_out + (size_t)b * NSTATE);
                out2[G0]     = make_ulonglong2(a0, b0);
                out2[G0 + 1] = make_ulonglong2(a1, b1);
                out2[G0 + 2] = make_ulonglong2(a2, b2);
                out2[G0 + 3] = make_ulonglong2(a3, b3);
                u64 q[8] = {a0, b0, a1, b1, a2, b2, a3, b3};
                float ssq = 0.f;
                #pragma unroll
                for (int j = 0; j < 8; j++) {
                    float2 f = *(float2*)&q[j];
                    ssq += f.x * f.x + f.y * f.y;
                }
                red[t] = ssq;
            } else {
                st2(sm, G0,     a0, b0); st2(sm, G0 + 1, a1, b1);
                st2(sm, G0 + 2, a2, b2); st2(sm, G0 + 3, a3, b3);
            }
        }
        __syncthreads();
    }

    if (t < 64) {
        probs_out[b * 64 + t] =
            red[4 * t] + red[4 * t + 1] + red[4 * t + 2] + red[4 * t + 3];
    }
}

extern "C" void kernel_launch(void* const* d_in, const int* in_sizes, int n_in,
                              void* d_out, int out_size) {
    const float* psi = (const float*)d_in[0];
    const int*   inp = (const int*)d_in[1];
    const float* uth = (const float*)d_in[2];
    const float* nth = (const float*)d_in[3];
    float* out = (float*)d_out;

    float* probs_out = out;
    float* psi_out   = out + BATCH * 64;

    precompute_kernel<<<(STAGES * 5 * 256 * 8 + 255) / 256, 256>>>(uth, nth);
    sim_kernel<<<BATCH, 256>>>(psi, inp, probs_out, psi_out);
}

// round 15
// speedup vs baseline: 1.0732x; 1.0732x over previous
#include <cuda_runtime.h>

#define W_      10
#define NSTATE  4096
#define BATCH   512
#define NIN     6
#define STAGES  2

typedef unsigned long long u64;

#define NEGB   0x8000000080000000ULL
#define MASKP  0x0000000080000000ULL
#define MASKM  0x8000000000000000ULL

// g_tab[(s*W + out)*1024 + g] = (cos(phi/2), sin(phi/2)); g = amp bits 11..2
__device__ float2 g_tab[STAGES * W_ * 1024];
__device__ float2 u_tab[STAGES * W_];

__global__ void precompute_kernel(const float* __restrict__ unitary_theta,
                                  const float* __restrict__ neuron_theta) {
    int idx = blockIdx.x * blockDim.x + threadIdx.x;
    if (idx < STAGES * W_ * 1024) {
        int g  = idx & 1023;
        int sn = idx >> 10;
        const float* th = neuron_theta + sn * (W_ + 1);
        float phi = th[W_];
        #pragma unroll
        for (int i = 0; i < W_; i++)
            if ((g >> (9 - i)) & 1) phi += th[i];
        float sv, cv;
        sincosf(phi * 0.5f, &sv, &cv);
        g_tab[idx] = make_float2(cv, sv);
    }
    if (idx < STAGES * W_) {
        float sv, cv;
        sincosf(unitary_theta[idx] * 0.5f, &sv, &cv);
        u_tab[idx] = make_float2(cv, sv);
    }
}

// ---- f32x2 primitives ----
__device__ __forceinline__ u64 pk2(float lo, float hi) {
    u64 r; asm("mov.b64 %0, {%1,%2};" : "=l"(r) : "f"(lo), "f"(hi)); return r;
}
__device__ __forceinline__ u64 bcast(float v) { return pk2(v, v); }
__device__ __forceinline__ u64 f2mul(u64 a, u64 b) {
    u64 r; asm("mul.rn.f32x2 %0, %1, %2;" : "=l"(r) : "l"(a), "l"(b)); return r;
}
__device__ __forceinline__ u64 f2fma(u64 a, u64 b, u64 c) {
    u64 r; asm("fma.rn.f32x2 %0, %1, %2, %3;" : "=l"(r) : "l"(a), "l"(b), "l"(c)); return r;
}
__device__ __forceinline__ u64 lswap(u64 a) {
    u64 r; asm("{.reg .b32 x,y; mov.b64 {x,y}, %1; mov.b64 %0, {y,x};}" : "=l"(r) : "l"(a)); return r;
}
__device__ __forceinline__ void xswapneg(u64& a, u64& b) {
    asm("{\n\t.reg .b32 al,ah,bl,bh;\n\t"
        "mov.b64 {al,ah}, %0;\n\t"
        "mov.b64 {bl,bh}, %1;\n\t"
        "neg.f32 bh, bh;\n\t"
        "mov.b64 %0, {al,bh};\n\t"
        "mov.b64 %1, {bl,ah};\n\t}"
        : "+l"(a), "+l"(b));
}

// ---- swizzle (proven conflict-free) ----
__device__ __forceinline__ int swG(int G) {
    return G ^ ( ((G >> 3) & 1)
               | (((G >> 4) & 1) << 1)
               | ((((G >> 5) ^ (G >> 4)) & 1) << 2) );
}
__device__ __forceinline__ int swE(int e) { return (swG(e >> 1) << 1) | (e & 1); }

__device__ __forceinline__ void ld2(const u64* sm, int g, u64& a, u64& b) {
    ulonglong2 v = *(const ulonglong2*)(sm + (swG(g) << 1)); a = v.x; b = v.y;
}
__device__ __forceinline__ void st2(u64* sm, int g, u64 a, u64 b) {
    *(ulonglong2*)(sm + (swG(g) << 1)) = make_ulonglong2(a, b);
}

// grp4p: RY(+phi) q10, CRY(sgn*pi) 10->11, RY(-phi) q10
__device__ __forceinline__ void grp4p(u64& qxy, u64& qzw,
                                      u64 cc, u64 ss, u64 nss, u64 umask) {
    u64 t01 = f2fma(cc, qxy, f2mul(nss, qzw));
    u64 t23 = f2fma(cc, qzw, f2mul(ss,  qxy));
    u64 u23 = lswap(t23) ^ umask;
    qxy = f2fma(cc, t01, f2mul(ss,  u23));
    qzw = f2fma(cc, u23, f2mul(nss, t01));
}
// full neuron on 8 amps (two packed groups)
__device__ __forceinline__ void neuron8p(u64& xy0, u64& zw0, u64& xy1, u64& zw1,
                                         float2 cs0, float2 cs1) {
    u64 cc0 = bcast(cs0.x), ss0 = bcast(cs0.y), nss0 = ss0 ^ NEGB;
    u64 cc1 = bcast(cs1.x), ss1 = bcast(cs1.y), nss1 = ss1 ^ NEGB;
    grp4p(xy0, zw0, cc0, ss0, nss0, MASKP);
    grp4p(xy1, zw1, cc1, ss1, nss1, MASKP);
    xswapneg(xy0, xy1);
    xswapneg(zw0, zw1);
    grp4p(xy0, zw0, cc0, ss0, nss0, MASKM);
    grp4p(xy1, zw1, cc1, ss1, nss1, MASKM);
}

// RY on bit `bit` of the 8-element u64 register index
__device__ __forceinline__ void ry8b(u64 R[8], int bit, float2 cs) {
    u64 cc = bcast(cs.x), ss = bcast(cs.y), nss = ss ^ NEGB;
    #pragma unroll
    for (int k = 0; k < 8; k++) {
        if (!((k >> bit) & 1)) {
            int k1 = k | (1 << bit);
            u64 a = R[k], b2 = R[k1];
            R[k]  = f2fma(cc, a, f2mul(nss, b2));
            R[k1] = f2fma(ss, a, f2mul(cc,  b2));
        }
    }
}

// group indices for the sweep whose neurons target amp bits PA, PA-1
template <int PA>
__device__ __forceinline__ void sweep_gidx(int t, int g[4]) {
    constexpr int PB = PA - 1;
    constexpr int LB = PB - 2;
    const int low  = t & ((1 << LB) - 1);
    const int high = t >> LB;
    const int gb   = low | (high << (PA - 1));
    g[0] = gb;
    g[1] = gb + (1 << (PB - 2));
    g[2] = gb + (1 << (PA - 2));
    g[3] = g[2] + (1 << (PB - 2));
}

// prefetch the 8 coefficients for a sweep (read-only; legal to hoist over barriers)
template <int PA>
__device__ __forceinline__ void load_coef(const float2* __restrict__ tabA,
                                          const float2* __restrict__ tabB,
                                          int t, float2 c[8]) {
    int g[4];
    sweep_gidx<PA>(t, g);
    #pragma unroll
    for (int j = 0; j < 4; j++) { c[j] = tabA[g[j]]; c[4 + j] = tabB[g[j]]; }
}

// neuron pair with prefetched coefficients c[0..3]=A@g0..g3, c[4..7]=B@g0..g3
template <int PA>
__device__ __forceinline__ void neuron_pairc(u64* sm, const float2 c[8], int t) {
    int g[4];
    sweep_gidx<PA>(t, g);
    u64 a0, b0, a1, b1, a2, b2, a3, b3;
    ld2(sm, g[0], a0, b0); ld2(sm, g[1], a1, b1);
    ld2(sm, g[2], a2, b2); ld2(sm, g[3], a3, b3);

    neuron8p(a0, b0, a2, b2, c[0], c[2]);   // A: g0,g2
    neuron8p(a1, b1, a3, b3, c[1], c[3]);   // A: g1,g3
    neuron8p(a0, b0, a1, b1, c[4], c[5]);   // B: g0,g1
    neuron8p(a2, b2, a3, b3, c[6], c[7]);   // B: g2,g3

    st2(sm, g[0], a0, b0); st2(sm, g[1], a1, b1);
    st2(sm, g[2], a2, b2); st2(sm, g[3], a3, b3);
}

__global__ void __launch_bounds__(256, 3) sim_kernel(
    const float* __restrict__ psi_in,
    const int*   __restrict__ inp,
    float*       __restrict__ probs_out,
    float*       __restrict__ psi_out)
{
    __shared__ __align__(16) u64 sm[NSTATE / 2];
    __shared__ float red[256];

    const int b = blockIdx.x;
    const int t = threadIdx.x;

    const int barP = 1 + ((t >> 5) & 1);   // ids 1,2 (parity groups, 128 thr)
    const int barQ = 3 + (t >> 6);         // ids 3..6 (2-warp groups, 64 thr)

    int mask = 0;
    #pragma unroll
    for (int l = 0; l < NIN; l++) mask |= (inp[l] & 1) << (11 - l);

    #pragma unroll
    for (int s = 0; s < STAGES; s++) {
        const float2* ut = &u_tab[s * W_];
        const float2* tb = &g_tab[(s * W_) << 10];

        // ---- U-A: RY lanes 0,1,2 (e bits 10,9,8). e = t | (k<<8).
        {
            u64 R[8];
            if (s == 0) {
                const float* in = psi_in + (size_t)b * NSTATE;
                #pragma unroll
                for (int k = 0; k < 8; k++) {
                    int e = t | (k << 8);
                    R[k] = *(const u64*)(in + ((e << 1) ^ mask));
                }
            } else {
                #pragma unroll
                for (int k = 0; k < 8; k++) R[k] = sm[swE(t | (k << 8))];
            }
            ry8b(R, 2, ut[0]); ry8b(R, 1, ut[1]); ry8b(R, 0, ut[2]);
            #pragma unroll
            for (int k = 0; k < 8; k++) sm[swE(t | (k << 8))] = R[k];
        }
        __syncthreads();

        // ---- U-B: RY lanes 3,4,5 (e bits 7,6,5). Warp-local.
        {
            const int base = (t & 31) | ((t >> 5) << 8);
            u64 R[8];
            #pragma unroll
            for (int k = 0; k < 8; k++) R[k] = sm[swE(base | (k << 5))];
            ry8b(R, 2, ut[3]); ry8b(R, 1, ut[4]); ry8b(R, 0, ut[5]);
            #pragma unroll
            for (int k = 0; k < 8; k++) sm[swE(base | (k << 5))] = R[k];
        }
        __syncwarp();

        // ---- U-C: RY lanes 6,7,8 (e bits 4,3,2) + lane 9 (e bit 1) via shfl.
        float2 cN[8];   // prefetched coefficients for the NEXT neuron sweep
        {
            const int base = (t & 3) | ((t >> 2) << 5);
            u64 R[8];
            #pragma unroll
            for (int k = 0; k < 8; k++) R[k] = sm[swE(base | (k << 2))];
            ry8b(R, 2, ut[6]); ry8b(R, 1, ut[7]); ry8b(R, 0, ut[8]);
            {
                u64 cc = bcast(ut[9].x);
                u64 sp = bcast((t & 2) ? ut[9].y : -ut[9].y);
                #pragma unroll
                for (int k = 0; k < 8; k++) {
                    u64 o = __shfl_xor_sync(0xffffffffu, R[k], 2);
                    R[k] = f2fma(cc, R[k], f2mul(sp, o));
                }
            }
            // prefetch pair<11> coefficients before the barrier
            load_coef<11>(tb + (0 << 10), tb + (1 << 10), t, cN);
            #pragma unroll
            for (int k = 0; k < 8; k++) sm[swE(base | (k << 2))] = R[k];
        }
        __syncthreads();

        // ---- neuron pairs, each prefetching the next sweep's coefficients
        {
            float2 cC[8];
            #pragma unroll
            for (int j = 0; j < 8; j++) cC[j] = cN[j];
            load_coef<9>(tb + (2 << 10), tb + (3 << 10), t, cN);
            neuron_pairc<11>(sm, cC, t);
        }
        asm volatile("bar.sync %0, 128;" :: "r"(barP) : "memory");
        {
            float2 cC[8];
            #pragma unroll
            for (int j = 0; j < 8; j++) cC[j] = cN[j];
            load_coef<7>(tb + (4 << 10), tb + (5 << 10), t, cN);
            neuron_pairc<9>(sm, cC, t);
        }
        asm volatile("bar.sync %0, 64;" :: "r"(barQ) : "memory");
        {
            float2 cC[8];
            #pragma unroll
            for (int j = 0; j < 8; j++) cC[j] = cN[j];
            load_coef<5>(tb + (6 << 10), tb + (7 << 10), t, cN);
            neuron_pairc<7>(sm, cC, t);
        }
        __syncwarp();
        {
            float2 cC[8];
            #pragma unroll
            for (int j = 0; j < 8; j++) cC[j] = cN[j];
            load_coef<3>(tb + (8 << 10), tb + (9 << 10), t, cN);
            neuron_pairc<5>(sm, cC, t);
        }
        __syncwarp();

        // ---- neurons 8,9 (sweep PA=3): 4 contiguous groups, prefetched in cN.
        {
            const int G0 = t << 2;
            u64 a0, b0, a1, b1, a2, b2, a3, b3;
            ld2(sm, G0,     a0, b0); ld2(sm, G0 + 1, a1, b1);
            ld2(sm, G0 + 2, a2, b2); ld2(sm, G0 + 3, a3, b3);

            neuron8p(a0, b0, a2, b2, cN[0], cN[2]);
            neuron8p(a1, b1, a3, b3, cN[1], cN[3]);
            neuron8p(a0, b0, a1, b1, cN[4], cN[5]);
            neuron8p(a2, b2, a3, b3, cN[6], cN[7]);

            if (s == STAGES - 1) {
                ulonglong2* out2 = (ulonglong2*)(psi_out + (size_t)b * NSTATE);
                out2[G0]     = make_ulonglong2(a0, b0);
                out2[G0 + 1] = make_ulonglong2(a1, b1);
                out2[G0 + 2] = make_ulonglong2(a2, b2);
                out2[G0 + 3] = make_ulonglong2(a3, b3);
                u64 q[8] = {a0, b0, a1, b1, a2, b2, a3, b3};
                float ssq = 0.f;
                #pragma unroll
                for (int j = 0; j < 8; j++) {
                    float2 f = *(float2*)&q[j];
                    ssq += f.x * f.x + f.y * f.y;
                }
                red[t] = ssq;
            } else {
                st2(sm, G0,     a0, b0); st2(sm, G0 + 1, a1, b1);
                st2(sm, G0 + 2, a2, b2); st2(sm, G0 + 3, a3, b3);
            }
        }
        __syncthreads();
    }

    if (t < 64) {
        probs_out[b * 64 + t] =
            red[4 * t] + red[4 * t + 1] + red[4 * t + 2] + red[4 * t + 3];
    }
}

extern "C" void kernel_launch(void* const* d_in, const int* in_sizes, int n_in,
                              void* d_out, int out_size) {
    const float* psi = (const float*)d_in[0];
    const int*   inp = (const int*)d_in[1];
    const float* uth = (const float*)d_in[2];
    const float* nth = (const float*)d_in[3];
    float* out = (float*)d_out;

    float* probs_out = out;
    float* psi_out   = out + BATCH * 64;

    precompute_kernel<<<(STAGES * W_ * 1024 + 255) / 256, 256>>>(uth, nth);
    sim_kernel<<<BATCH, 256>>>(psi, inp, probs_out, psi_out);
}

// round 16
// speedup vs baseline: 1.0831x; 1.0092x over previous
#include <cuda_runtime.h>

#define W_      10
#define NSTATE  4096
#define BATCH   512
#define NIN     6
#define STAGES  2

typedef unsigned long long u64;

#define NEGB   0x8000000080000000ULL
#define MASKP  0x0000000080000000ULL
#define MASKM  0x8000000000000000ULL

// g_tab[(s*W + out)*1024 + g] = (cos(phi/2), sin(phi/2)); g = amp bits 11..2
__device__ float2 g_tab[STAGES * W_ * 1024];
__device__ float2 u_tab[STAGES * W_];

__global__ void precompute_kernel(const float* __restrict__ unitary_theta,
                                  const float* __restrict__ neuron_theta) {
    int idx = blockIdx.x * blockDim.x + threadIdx.x;
    if (idx < STAGES * W_ * 1024) {
        int g  = idx & 1023;
        int sn = idx >> 10;
        const float* th = neuron_theta + sn * (W_ + 1);
        float phi = th[W_];
        #pragma unroll
        for (int i = 0; i < W_; i++)
            if ((g >> (9 - i)) & 1) phi += th[i];
        float sv, cv;
        sincosf(phi * 0.5f, &sv, &cv);
        g_tab[idx] = make_float2(cv, sv);
    }
    if (idx < STAGES * W_) {
        float sv, cv;
        sincosf(unitary_theta[idx] * 0.5f, &sv, &cv);
        u_tab[idx] = make_float2(cv, sv);
    }
}

// ---- f32x2 primitives ----
__device__ __forceinline__ u64 pk2(float lo, float hi) {
    u64 r; asm("mov.b64 %0, {%1,%2};" : "=l"(r) : "f"(lo), "f"(hi)); return r;
}
__device__ __forceinline__ u64 bcast(float v) { return pk2(v, v); }
__device__ __forceinline__ u64 f2mul(u64 a, u64 b) {
    u64 r; asm("mul.rn.f32x2 %0, %1, %2;" : "=l"(r) : "l"(a), "l"(b)); return r;
}
__device__ __forceinline__ u64 f2fma(u64 a, u64 b, u64 c) {
    u64 r; asm("fma.rn.f32x2 %0, %1, %2, %3;" : "=l"(r) : "l"(a), "l"(b), "l"(c)); return r;
}
__device__ __forceinline__ u64 lswap(u64 a) {
    u64 r; asm("{.reg .b32 x,y; mov.b64 {x,y}, %1; mov.b64 %0, {y,x};}" : "=l"(r) : "l"(a)); return r;
}
__device__ __forceinline__ void xswapneg(u64& a, u64& b) {
    asm("{\n\t.reg .b32 al,ah,bl,bh;\n\t"
        "mov.b64 {al,ah}, %0;\n\t"
        "mov.b64 {bl,bh}, %1;\n\t"
        "neg.f32 bh, bh;\n\t"
        "mov.b64 %0, {al,bh};\n\t"
        "mov.b64 %1, {bl,ah};\n\t}"
        : "+l"(a), "+l"(b));
}

// ---- swizzle (proven conflict-free) ----
__device__ __forceinline__ int swG(int G) {
    return G ^ ( ((G >> 3) & 1)
               | (((G >> 4) & 1) << 1)
               | ((((G >> 5) ^ (G >> 4)) & 1) << 2) );
}
__device__ __forceinline__ int swE(int e) { return (swG(e >> 1) << 1) | (e & 1); }

__device__ __forceinline__ void ld2(const u64* sm, int g, u64& a, u64& b) {
    ulonglong2 v = *(const ulonglong2*)(sm + (swG(g) << 1)); a = v.x; b = v.y;
}
__device__ __forceinline__ void st2(u64* sm, int g, u64 a, u64 b) {
    *(ulonglong2*)(sm + (swG(g) << 1)) = make_ulonglong2(a, b);
}

// grp4p: RY(+phi) q10, CRY(sgn*pi) 10->11, RY(-phi) q10
__device__ __forceinline__ void grp4p(u64& qxy, u64& qzw,
                                      u64 cc, u64 ss, u64 nss, u64 umask) {
    u64 t01 = f2fma(cc, qxy, f2mul(nss, qzw));
    u64 t23 = f2fma(cc, qzw, f2mul(ss,  qxy));
    u64 u23 = lswap(t23) ^ umask;
    qxy = f2fma(cc, t01, f2mul(ss,  u23));
    qzw = f2fma(cc, u23, f2mul(nss, t01));
}
// full neuron on 8 amps (two packed groups)
__device__ __forceinline__ void neuron8p(u64& xy0, u64& zw0, u64& xy1, u64& zw1,
                                         float2 cs0, float2 cs1) {
    u64 cc0 = bcast(cs0.x), ss0 = bcast(cs0.y), nss0 = ss0 ^ NEGB;
    u64 cc1 = bcast(cs1.x), ss1 = bcast(cs1.y), nss1 = ss1 ^ NEGB;
    grp4p(xy0, zw0, cc0, ss0, nss0, MASKP);
    grp4p(xy1, zw1, cc1, ss1, nss1, MASKP);
    xswapneg(xy0, xy1);
    xswapneg(zw0, zw1);
    grp4p(xy0, zw0, cc0, ss0, nss0, MASKM);
    grp4p(xy1, zw1, cc1, ss1, nss1, MASKM);
}

// RY on bit `bit` of the 8-element u64 register index
__device__ __forceinline__ void ry8b(u64 R[8], int bit, float2 cs) {
    u64 cc = bcast(cs.x), ss = bcast(cs.y), nss = ss ^ NEGB;
    #pragma unroll
    for (int k = 0; k < 8; k++) {
        if (!((k >> bit) & 1)) {
            int k1 = k | (1 << bit);
            u64 a = R[k], b2 = R[k1];
            R[k]  = f2fma(cc, a, f2mul(nss, b2));
            R[k1] = f2fma(ss, a, f2mul(cc,  b2));
        }
    }
}

// Neuron pair: neurons targeting amp bits PA, PA-1; thread owns amp bits {PA,PA-1,1,0}
template <int PA>
__device__ __forceinline__ void neuron_pairp(u64* sm,
                                             const float2* __restrict__ tabA,
                                             const float2* __restrict__ tabB,
                                             int t) {
    constexpr int PB = PA - 1;
    constexpr int LB = PB - 2;
    const int low  = t & ((1 << LB) - 1);
    const int high = t >> LB;
    const int gb   = low | (high << (PA - 1));

    const int g00 = gb;
    const int g01 = gb + (1 << (PB - 2));
    const int g10 = gb + (1 << (PA - 2));
    const int g11 = g10 + (1 << (PB - 2));

    u64 a0, b0, a1, b1, a2, b2, a3, b3;
    ld2(sm, g00, a0, b0); ld2(sm, g01, a1, b1);
    ld2(sm, g10, a2, b2); ld2(sm, g11, a3, b3);

    neuron8p(a0, b0, a2, b2, tabA[g00], tabA[g10]);
    neuron8p(a1, b1, a3, b3, tabA[g01], tabA[g11]);
    neuron8p(a0, b0, a1, b1, tabB[g00], tabB[g01]);
    neuron8p(a2, b2, a3, b3, tabB[g10], tabB[g11]);

    st2(sm, g00, a0, b0); st2(sm, g01, a1, b1);
    st2(sm, g10, a2, b2); st2(sm, g11, a3, b3);
}

__global__ void __launch_bounds__(256, 4) sim_kernel(
    const float* __restrict__ psi_in,
    const int*   __restrict__ inp,
    float*       __restrict__ probs_out,
    float*       __restrict__ psi_out)
{
    __shared__ __align__(16) u64 sm[NSTATE / 2];
    __shared__ float red[256];

    const int b = blockIdx.x;
    const int t = threadIdx.x;

    const int barP = 1 + ((t >> 5) & 1);   // ids 1,2 (parity groups, 128 thr)
    const int barQ = 3 + (t >> 6);         // ids 3..6 (2-warp groups, 64 thr)

    int mask = 0;
    #pragma unroll
    for (int l = 0; l < NIN; l++) mask |= (inp[l] & 1) << (11 - l);

    #pragma unroll
    for (int s = 0; s < STAGES; s++) {
        const float2* ut = &u_tab[s * W_];

        // ---- U-A: RY lanes 0,1,2 (e bits 10,9,8). e = t | (k<<8).
        {
            u64 R[8];
            if (s == 0) {
                const float* in = psi_in + (size_t)b * NSTATE;
                #pragma unroll
                for (int k = 0; k < 8; k++) {
                    int e = t | (k << 8);
                    R[k] = *(const u64*)(in + ((e << 1) ^ mask));
                }
            } else {
                #pragma unroll
                for (int k = 0; k < 8; k++) R[k] = sm[swE(t | (k << 8))];
            }
            ry8b(R, 2, ut[0]); ry8b(R, 1, ut[1]); ry8b(R, 0, ut[2]);
            #pragma unroll
            for (int k = 0; k < 8; k++) sm[swE(t | (k << 8))] = R[k];
        }
        __syncthreads();

        // ---- U-BC (merged): lanes 3,4,5 (e bits 7,6,5 = reg bits) in registers,
        //      lanes 6,7,8,9 (e bits 4,3,2,1 = t bits 4,3,2,1) via warp shuffle.
        //      All unitary RYs commute (disjoint qubits), so order is free.
        {
            const int base = (t & 31) | ((t >> 5) << 8);
            u64 R[8];
            #pragma unroll
            for (int k = 0; k < 8; k++) R[k] = sm[swE(base | (k << 5))];
            ry8b(R, 2, ut[3]); ry8b(R, 1, ut[4]); ry8b(R, 0, ut[5]);
            #pragma unroll
            for (int l = 0; l < 4; l++) {
                const int shift = 16 >> l;          // lanes 6,7,8,9 -> 16,8,4,2
                float2 cs = ut[6 + l];
                u64 cc = bcast(cs.x);
                u64 sp = bcast((t & shift) ? cs.y : -cs.y);
                #pragma unroll
                for (int k = 0; k < 8; k++) {
                    u64 o = __shfl_xor_sync(0xffffffffu, R[k], shift);
                    R[k] = f2fma(cc, R[k], f2mul(sp, o));
                }
            }
            #pragma unroll
            for (int k = 0; k < 8; k++) sm[swE(base | (k << 5))] = R[k];
        }
        __syncthreads();

        const float2* tb = &g_tab[(s * W_) << 10];

        // ---- neuron pairs
        neuron_pairp<11>(sm, tb + (0 << 10), tb + (1 << 10), t);
        asm volatile("bar.sync %0, 128;" :: "r"(barP) : "memory");
        neuron_pairp<9 >(sm, tb + (2 << 10), tb + (3 << 10), t);
        asm volatile("bar.sync %0, 64;" :: "r"(barQ) : "memory");
        neuron_pairp<7 >(sm, tb + (4 << 10), tb + (5 << 10), t); __syncwarp();
        neuron_pairp<5 >(sm, tb + (6 << 10), tb + (7 << 10), t); __syncwarp();

        // ---- neurons 8,9 (group bits 1,0): 4 contiguous groups (warp-local reads).
        {
            const float2* tabA = tb + (8 << 10);
            const float2* tabB = tb + (9 << 10);
            const int G0 = t << 2;
            u64 a0, b0, a1, b1, a2, b2, a3, b3;
            ld2(sm, G0,     a0, b0); ld2(sm, G0 + 1, a1, b1);
            ld2(sm, G0 + 2, a2, b2); ld2(sm, G0 + 3, a3, b3);

            neuron8p(a0, b0, a2, b2, tabA[G0],     tabA[G0 + 2]);
            neuron8p(a1, b1, a3, b3, tabA[G0 + 1], tabA[G0 + 3]);
            neuron8p(a0, b0, a1, b1, tabB[G0],     tabB[G0 + 1]);
            neuron8p(a2, b2, a3, b3, tabB[G0 + 2], tabB[G0 + 3]);

            if (s == STAGES - 1) {
                ulonglong2* out2 = (ulonglong2*)(psi_out + (size_t)b * NSTATE);
                out2[G0]     = make_ulonglong2(a0, b0);
                out2[G0 + 1] = make_ulonglong2(a1, b1);
                out2[G0 + 2] = make_ulonglong2(a2, b2);
                out2[G0 + 3] = make_ulonglong2(a3, b3);
                u64 q[8] = {a0, b0, a1, b1, a2, b2, a3, b3};
                float ssq = 0.f;
                #pragma unroll
                for (int j = 0; j < 8; j++) {
                    float2 f = *(float2*)&q[j];
                    ssq += f.x * f.x + f.y * f.y;
                }
                red[t] = ssq;
            } else {
                st2(sm, G0,     a0, b0); st2(sm, G0 + 1, a1, b1);
                st2(sm, G0 + 2, a2, b2); st2(sm, G0 + 3, a3, b3);
            }
        }
        __syncthreads();
    }

    if (t < 64) {
        probs_out[b * 64 + t] =
            red[4 * t] + red[4 * t + 1] + red[4 * t + 2] + red[4 * t + 3];
    }
}

extern "C" void kernel_launch(void* const* d_in, const int* in_sizes, int n_in,
                              void* d_out, int out_size) {
    const float* psi = (const float*)d_in[0];
    const int*   inp = (const int*)d_in[1];
    const float* uth = (const float*)d_in[2];
    const float* nth = (const float*)d_in[3];
    float* out = (float*)d_out;

    float* probs_out = out;
    float* psi_out   = out + BATCH * 64;

    precompute_kernel<<<(STAGES * W_ * 1024 + 255) / 256, 256>>>(uth, nth);
    sim_kernel<<<BATCH, 256>>>(psi, inp, probs_out, psi_out);
}

// round 17
// speedup vs baseline: 1.0842x; 1.0010x over previous
#include <cuda_runtime.h>

#define W_      10
#define NSTATE  4096
#define BATCH   512
#define NIN     6
#define STAGES  2

typedef unsigned long long u64;

#define NEGB   0x8000000080000000ULL
#define MASKP  0x0000000080000000ULL
#define MASKM  0x8000000000000000ULL

// g_tab[(s*W + out)*1024 + g] = (cos(phi/2), sin(phi/2)); g = amp bits 11..2
__device__ float2 g_tab[STAGES * W_ * 1024];
__device__ float2 u_tab[STAGES * W_];

__global__ void precompute_kernel(const float* __restrict__ unitary_theta,
                                  const float* __restrict__ neuron_theta) {
    int idx = blockIdx.x * blockDim.x + threadIdx.x;
    if (idx < STAGES * W_ * 1024) {
        int g  = idx & 1023;
        int sn = idx >> 10;
        const float* th = neuron_theta + sn * (W_ + 1);
        float phi = th[W_];
        #pragma unroll
        for (int i = 0; i < W_; i++)
            if ((g >> (9 - i)) & 1) phi += th[i];
        float sv, cv;
        sincosf(phi * 0.5f, &sv, &cv);
        g_tab[idx] = make_float2(cv, sv);
    }
    if (idx < STAGES * W_) {
        float sv, cv;
        sincosf(unitary_theta[idx] * 0.5f, &sv, &cv);
        u_tab[idx] = make_float2(cv, sv);
    }
}

// ---- f32x2 primitives ----
__device__ __forceinline__ u64 pk2(float lo, float hi) {
    u64 r; asm("mov.b64 %0, {%1,%2};" : "=l"(r) : "f"(lo), "f"(hi)); return r;
}
__device__ __forceinline__ u64 bcast(float v) { return pk2(v, v); }
__device__ __forceinline__ u64 f2mul(u64 a, u64 b) {
    u64 r; asm("mul.rn.f32x2 %0, %1, %2;" : "=l"(r) : "l"(a), "l"(b)); return r;
}
__device__ __forceinline__ u64 f2fma(u64 a, u64 b, u64 c) {
    u64 r; asm("fma.rn.f32x2 %0, %1, %2, %3;" : "=l"(r) : "l"(a), "l"(b), "l"(c)); return r;
}
__device__ __forceinline__ u64 lswap(u64 a) {
    u64 r; asm("{.reg .b32 x,y; mov.b64 {x,y}, %1; mov.b64 %0, {y,x};}" : "=l"(r) : "l"(a)); return r;
}
__device__ __forceinline__ void xswapneg(u64& a, u64& b) {
    asm("{\n\t.reg .b32 al,ah,bl,bh;\n\t"
        "mov.b64 {al,ah}, %0;\n\t"
        "mov.b64 {bl,bh}, %1;\n\t"
        "neg.f32 bh, bh;\n\t"
        "mov.b64 %0, {al,bh};\n\t"
        "mov.b64 %1, {bl,ah};\n\t}"
        : "+l"(a), "+l"(b));
}

// ---- swizzle (proven conflict-free) ----
__device__ __forceinline__ int swG(int G) {
    return G ^ ( ((G >> 3) & 1)
               | (((G >> 4) & 1) << 1)
               | ((((G >> 5) ^ (G >> 4)) & 1) << 2) );
}
__device__ __forceinline__ int swE(int e) { return (swG(e >> 1) << 1) | (e & 1); }

__device__ __forceinline__ void ld2(const u64* sm, int g, u64& a, u64& b) {
    ulonglong2 v = *(const ulonglong2*)(sm + (swG(g) << 1)); a = v.x; b = v.y;
}
__device__ __forceinline__ void st2(u64* sm, int g, u64 a, u64 b) {
    *(ulonglong2*)(sm + (swG(g) << 1)) = make_ulonglong2(a, b);
}

// grp4p: RY(+phi) q10, CRY(sgn*pi) 10->11, RY(-phi) q10
__device__ __forceinline__ void grp4p(u64& qxy, u64& qzw,
                                      u64 cc, u64 ss, u64 nss, u64 umask) {
    u64 t01 = f2fma(cc, qxy, f2mul(nss, qzw));
    u64 t23 = f2fma(cc, qzw, f2mul(ss,  qxy));
    u64 u23 = lswap(t23) ^ umask;
    qxy = f2fma(cc, t01, f2mul(ss,  u23));
    qzw = f2fma(cc, u23, f2mul(nss, t01));
}
// full neuron on 8 amps (two packed groups)
__device__ __forceinline__ void neuron8p(u64& xy0, u64& zw0, u64& xy1, u64& zw1,
                                         float2 cs0, float2 cs1) {
    u64 cc0 = bcast(cs0.x), ss0 = bcast(cs0.y), nss0 = ss0 ^ NEGB;
    u64 cc1 = bcast(cs1.x), ss1 = bcast(cs1.y), nss1 = ss1 ^ NEGB;
    grp4p(xy0, zw0, cc0, ss0, nss0, MASKP);
    grp4p(xy1, zw1, cc1, ss1, nss1, MASKP);
    xswapneg(xy0, xy1);
    xswapneg(zw0, zw1);
    grp4p(xy0, zw0, cc0, ss0, nss0, MASKM);
    grp4p(xy1, zw1, cc1, ss1, nss1, MASKM);
}

// RY across two u64 registers (same coefficient both lanes)
__device__ __forceinline__ void rypu(u64& a, u64& b, u64 cc, u64 ss, u64 nss) {
    u64 na = f2fma(cc, a, f2mul(nss, b));
    u64 nb = f2fma(ss, a, f2mul(cc,  b));
    a = na; b = nb;
}

// RY on bit `bit` of the 8-element u64 register index
__device__ __forceinline__ void ry8b(u64 R[8], int bit, float2 cs) {
    u64 cc = bcast(cs.x), ss = bcast(cs.y), nss = ss ^ NEGB;
    #pragma unroll
    for (int k = 0; k < 8; k++) {
        if (!((k >> bit) & 1)) {
            int k1 = k | (1 << bit);
            u64 a = R[k], b2 = R[k1];
            R[k]  = f2fma(cc, a, f2mul(nss, b2));
            R[k1] = f2fma(ss, a, f2mul(cc,  b2));
        }
    }
}

// Neuron pair: neurons targeting amp bits PA, PA-1; thread owns amp bits {PA,PA-1,1,0}
template <int PA>
__device__ __forceinline__ void neuron_pairp(u64* sm,
                                             const float2* __restrict__ tabA,
                                             const float2* __restrict__ tabB,
                                             int t) {
    constexpr int PB = PA - 1;
    constexpr int LB = PB - 2;
    const int low  = t & ((1 << LB) - 1);
    const int high = t >> LB;
    const int gb   = low | (high << (PA - 1));

    const int g00 = gb;
    const int g01 = gb + (1 << (PB - 2));
    const int g10 = gb + (1 << (PA - 2));
    const int g11 = g10 + (1 << (PB - 2));

    u64 a0, b0, a1, b1, a2, b2, a3, b3;
    ld2(sm, g00, a0, b0); ld2(sm, g01, a1, b1);
    ld2(sm, g10, a2, b2); ld2(sm, g11, a3, b3);

    neuron8p(a0, b0, a2, b2, tabA[g00], tabA[g10]);
    neuron8p(a1, b1, a3, b3, tabA[g01], tabA[g11]);
    neuron8p(a0, b0, a1, b1, tabB[g00], tabB[g01]);
    neuron8p(a2, b2, a3, b3, tabB[g10], tabB[g11]);

    st2(sm, g00, a0, b0); st2(sm, g01, a1, b1);
    st2(sm, g10, a2, b2); st2(sm, g11, a3, b3);
}

// pair<11> sweep with the 7 absorbable unitary RYs applied at its head:
// lanes 0,1 on the register dims (G bits 9,8), lanes 5..9 via warp shuffle
// (t bits 4..0 = e bits 5..1). All unitary RYs commute, and all 10 complete
// before neuron 0 (lanes 2,3,4 were done in sweep1).
__device__ __forceinline__ void pair11_with_unitary(u64* sm,
                                                    const float2* __restrict__ ut,
                                                    const float2* __restrict__ tabA,
                                                    const float2* __restrict__ tabB,
                                                    int t) {
    const int gb  = t;                 // PA=11: G bits 7..0 = t bits 7..0
    const int g00 = gb;
    const int g01 = gb + (1 << 8);     // G bit 8 = lane 1 dim
    const int g10 = gb + (1 << 9);     // G bit 9 = lane 0 dim
    const int g11 = g10 + (1 << 8);

    u64 a0, b0, a1, b1, a2, b2, a3, b3;
    ld2(sm, g00, a0, b0); ld2(sm, g01, a1, b1);
    ld2(sm, g10, a2, b2); ld2(sm, g11, a3, b3);

    // unitary lane 0 (G bit 9): pairs (q00,q10),(q01,q11)
    {
        u64 cc = bcast(ut[0].x), ss = bcast(ut[0].y), nss = ss ^ NEGB;
        rypu(a0, a2, cc, ss, nss); rypu(b0, b2, cc, ss, nss);
        rypu(a1, a3, cc, ss, nss); rypu(b1, b3, cc, ss, nss);
    }
    // unitary lane 1 (G bit 8): pairs (q00,q01),(q10,q11)
    {
        u64 cc = bcast(ut[1].x), ss = bcast(ut[1].y), nss = ss ^ NEGB;
        rypu(a0, a1, cc, ss, nss); rypu(b0, b1, cc, ss, nss);
        rypu(a2, a3, cc, ss, nss); rypu(b2, b3, cc, ss, nss);
    }
    // unitary lanes 5..9 via shuffle: shifts 16,8,4,2,1
    #pragma unroll
    for (int l = 0; l < 5; l++) {
        const int shift = 16 >> l;
        float2 cs = ut[5 + l];
        u64 cc = bcast(cs.x);
        u64 sp = bcast((t & shift) ? cs.y : -cs.y);
        u64 o;
        o = __shfl_xor_sync(0xffffffffu, a0, shift); a0 = f2fma(cc, a0, f2mul(sp, o));
        o = __shfl_xor_sync(0xffffffffu, b0, shift); b0 = f2fma(cc, b0, f2mul(sp, o));
        o = __shfl_xor_sync(0xffffffffu, a1, shift); a1 = f2fma(cc, a1, f2mul(sp, o));
        o = __shfl_xor_sync(0xffffffffu, b1, shift); b1 = f2fma(cc, b1, f2mul(sp, o));
        o = __shfl_xor_sync(0xffffffffu, a2, shift); a2 = f2fma(cc, a2, f2mul(sp, o));
        o = __shfl_xor_sync(0xffffffffu, b2, shift); b2 = f2fma(cc, b2, f2mul(sp, o));
        o = __shfl_xor_sync(0xffffffffu, a3, shift); a3 = f2fma(cc, a3, f2mul(sp, o));
        o = __shfl_xor_sync(0xffffffffu, b3, shift); b3 = f2fma(cc, b3, f2mul(sp, o));
    }

    // neurons 0,1
    neuron8p(a0, b0, a2, b2, tabA[g00], tabA[g10]);
    neuron8p(a1, b1, a3, b3, tabA[g01], tabA[g11]);
    neuron8p(a0, b0, a1, b1, tabB[g00], tabB[g01]);
    neuron8p(a2, b2, a3, b3, tabB[g10], tabB[g11]);

    st2(sm, g00, a0, b0); st2(sm, g01, a1, b1);
    st2(sm, g10, a2, b2); st2(sm, g11, a3, b3);
}

__global__ void __launch_bounds__(256, 4) sim_kernel(
    const float* __restrict__ psi_in,
    const int*   __restrict__ inp,
    float*       __restrict__ probs_out,
    float*       __restrict__ psi_out)
{
    __shared__ __align__(16) u64 sm[NSTATE / 2];
    __shared__ float red[256];

    const int b = blockIdx.x;
    const int t = threadIdx.x;

    const int barP = 1 + ((t >> 5) & 1);   // ids 1,2 (parity groups, 128 thr)
    const int barQ = 3 + (t >> 6);         // ids 3..6 (2-warp groups, 64 thr)

    int mask = 0;
    #pragma unroll
    for (int l = 0; l < NIN; l++) mask |= (inp[l] & 1) << (11 - l);

    #pragma unroll
    for (int s = 0; s < STAGES; s++) {
        const float2* ut = &u_tab[s * W_];

        // ---- sweep1: unitary lanes 2,3,4 (reg dims e bits 8,7,6).
        //      e = (t&63) | (k<<6) | ((t>>6)<<9). Stage 0 fuses global load+bitflip.
        {
            const int base = (t & 63) | ((t >> 6) << 9);
            u64 R[8];
            if (s == 0) {
                const float* in = psi_in + (size_t)b * NSTATE;
                #pragma unroll
                for (int k = 0; k < 8; k++) {
                    int e = base | (k << 6);
                    R[k] = *(const u64*)(in + ((e << 1) ^ mask));
                }
            } else {
                #pragma unroll
                for (int k = 0; k < 8; k++) R[k] = sm[swE(base | (k << 6))];
            }
            ry8b(R, 2, ut[2]); ry8b(R, 1, ut[3]); ry8b(R, 0, ut[4]);
            #pragma unroll
            for (int k = 0; k < 8; k++) sm[swE(base | (k << 6))] = R[k];
        }
        __syncthreads();

        const float2* tb = &g_tab[(s * W_) << 10];

        // ---- pair<11> with unitary head (lanes 0,1 + 5..9), then neurons 0,1
        pair11_with_unitary(sm, ut, tb + (0 << 10), tb + (1 << 10), t);
        asm volatile("bar.sync %0, 128;" :: "r"(barP) : "memory");
        neuron_pairp<9 >(sm, tb + (2 << 10), tb + (3 << 10), t);
        asm volatile("bar.sync %0, 64;" :: "r"(barQ) : "memory");
        neuron_pairp<7 >(sm, tb + (4 << 10), tb + (5 << 10), t); __syncwarp();
        neuron_pairp<5 >(sm, tb + (6 << 10), tb + (7 << 10), t); __syncwarp();

        // ---- neurons 8,9 (group bits 1,0): 4 contiguous groups (warp-local reads).
        {
            const float2* tabA = tb + (8 << 10);
            const float2* tabB = tb + (9 << 10);
            const int G0 = t << 2;
            u64 a0, b0, a1, b1, a2, b2, a3, b3;
            ld2(sm, G0,     a0, b0); ld2(sm, G0 + 1, a1, b1);
            ld2(sm, G0 + 2, a2, b2); ld2(sm, G0 + 3, a3, b3);

            neuron8p(a0, b0, a2, b2, tabA[G0],     tabA[G0 + 2]);
            neuron8p(a1, b1, a3, b3, tabA[G0 + 1], tabA[G0 + 3]);
            neuron8p(a0, b0, a1, b1, tabB[G0],     tabB[G0 + 1]);
            neuron8p(a2, b2, a3, b3, tabB[G0 + 2], tabB[G0 + 3]);

            if (s == STAGES - 1) {
                ulonglong2* out2 = (ulonglong2*)(psi_out + (size_t)b * NSTATE);
                out2[G0]     = make_ulonglong2(a0, b0);
                out2[G0 + 1] = make_ulonglong2(a1, b1);
                out2[G0 + 2] = make_ulonglong2(a2, b2);
                out2[G0 + 3] = make_ulonglong2(a3, b3);
                u64 q[8] = {a0, b0, a1, b1, a2, b2, a3, b3};
                float ssq = 0.f;
                #pragma unroll
                for (int j = 0; j < 8; j++) {
                    float2 f = *(float2*)&q[j];
                    ssq += f.x * f.x + f.y * f.y;
                }
                red[t] = ssq;
            } else {
                st2(sm, G0,     a0, b0); st2(sm, G0 + 1, a1, b1);
                st2(sm, G0 + 2, a2, b2); st2(sm, G0 + 3, a3, b3);
            }
        }
        __syncthreads();
    }

    if (t < 64) {
        probs_out[b * 64 + t] =
            red[4 * t] + red[4 * t + 1] + red[4 * t + 2] + red[4 * t + 3];
    }
}

extern "C" void kernel_launch(void* const* d_in, const int* in_sizes, int n_in,
                              void* d_out, int out_size) {
    const float* psi = (const float*)d_in[0];
    const int*   inp = (const int*)d_in[1];
    const float* uth = (const float*)d_in[2];
    const float* nth = (const float*)d_in[3];
    float* out = (float*)d_out;

    float* probs_out = out;
    float* psi_out   = out + BATCH * 64;

    precompute_kernel<<<(STAGES * W_ * 1024 + 255) / 256, 256>>>(uth, nth);
    sim_kernel<<<BATCH, 256>>>(psi, inp, probs_out, psi_out);
}